// round 4
// baseline (speedup 1.0000x reference)
#include <cuda_runtime.h>
#include <cuda_bf16.h>
#include <cstdint>

// URPE: out[b,h,i,j] = attention_probs[b,h,i,j] * toe[h,i,j]
// toe[h,i,j] = w[h, L + j - i] if j >= i else w[h, i - j].
//
// B=2, H=16, L=2048. HBM-bound streaming multiply (512 MB in + 512 MB out),
// traffic already at its 1.074 GB floor.
// R3: 256-bit global loads/stores (sm_100+ ld/st.global.v8.f32) — same bytes
// per thread as R2 but half the LDG/STG instructions and wider DRAM bursts.

static constexpr int LDIM = 2048;
static constexpr int HDIM = 16;
static constexpr int BDIM = 2;
static constexpr int V8_PER_ROW = LDIM / 8;             // 256 float8 per row
static constexpr long long NV8 =
    (long long)BDIM * HDIM * LDIM * LDIM / 8;           // 16,777,216
static constexpr int THREADS = 256;
static constexpr int ILP = 4;                           // float8s per thread

struct __align__(32) f8 { float v[8]; };

__device__ __forceinline__ f8 ldg256_cs(const f8* p) {
    f8 r;
    asm volatile(
        "ld.global.cs.v8.f32 {%0, %1, %2, %3, %4, %5, %6, %7}, [%8];"
        : "=f"(r.v[0]), "=f"(r.v[1]), "=f"(r.v[2]), "=f"(r.v[3]),
          "=f"(r.v[4]), "=f"(r.v[5]), "=f"(r.v[6]), "=f"(r.v[7])
        : "l"(p));
    return r;
}

__device__ __forceinline__ void stg256_cs(f8* p, const f8& r) {
    asm volatile(
        "st.global.cs.v8.f32 [%0], {%1, %2, %3, %4, %5, %6, %7, %8};"
        :: "l"(p),
           "f"(r.v[0]), "f"(r.v[1]), "f"(r.v[2]), "f"(r.v[3]),
           "f"(r.v[4]), "f"(r.v[5]), "f"(r.v[6]), "f"(r.v[7])
        : "memory");
}

__global__ __launch_bounds__(THREADS)
void urpe_mul_kernel(const f8* __restrict__ probs,
                     const float* __restrict__ w,
                     f8* __restrict__ out) {
    // Block covers ILP*THREADS = 1024 consecutive float8 (4 full rows).
    // Thread t owns vids base + k*256 — every wave of 256 lanes is coalesced
    // (256 lanes x 32 B = 8 KB contiguous per instruction wave).
    unsigned int base = blockIdx.x * (THREADS * ILP) + threadIdx.x;

    // Phase 1: front-batch the 4 independent 256-bit stream loads.
    f8 v[ILP];
#pragma unroll
    for (int k = 0; k < ILP; k++) {
        v[k] = ldg256_cs(&probs[base + k * THREADS]);
    }

    // Phase 2: weight gather + multiply (weight table = 256 KB, L1/L2-hot).
#pragma unroll
    for (int k = 0; k < ILP; k++) {
        unsigned int vid = base + k * THREADS;
        int j0 = (vid & (V8_PER_ROW - 1)) << 3;   // starting j of this float8
        int i  = (vid >> 8)  & (LDIM - 1);
        int h  = (vid >> 19) & (HDIM - 1);
        const float* __restrict__ wh = w + h * (2 * LDIM);

        int d = j0 - i;
#pragma unroll
        for (int e = 0; e < 8; e++) {
            int de = d + e;
            int oe = (de >= 0) ? (LDIM + de) : -de;
            v[k].v[e] *= __ldg(wh + oe);
        }
    }

    // Phase 3: 256-bit streaming stores.
#pragma unroll
    for (int k = 0; k < ILP; k++) {
        stg256_cs(&out[base + k * THREADS], v[k]);
    }
}

extern "C" void kernel_launch(void* const* d_in, const int* in_sizes, int n_in,
                              void* d_out, int out_size) {
    const f8*    probs = (const f8*)d_in[0];    // attention_probs [B,H,L,L] f32
    const float* w     = (const float*)d_in[1]; // urpe_weight_    [H,2L]   f32
    f8*          out   = (f8*)d_out;

    const int blocks = (int)(NV8 / (THREADS * ILP));   // 16384, exact
    urpe_mul_kernel<<<blocks, THREADS>>>(probs, w, out);
}

// round 5
// speedup vs baseline: 1.0188x; 1.0188x over previous
#include <cuda_runtime.h>
#include <cuda_bf16.h>

// URPE: out[b,h,i,j] = attention_probs[b,h,i,j] * toe[h,i,j]
// toe[h,i,j] = g[h, L + j - i],  g[h,m] = (m >= L) ? w[h,m] : w[h,L-m].
//
// B=2, H=16, L=2048. HBM-bound streaming multiply (512 MB in + 512 MB out).
// R4: 8 rows per block share one smem-staged window of g (L+8 floats),
// cutting global weight loads ~8x to free L1tex wavefronts for the stream.
// Smem uses +t/32 pad swizzle -> conflict-free scalar LDS (lane stride 4).

static constexpr int LDIM    = 2048;
static constexpr int HDIM    = 16;
static constexpr int BDIM    = 2;
static constexpr int THREADS = 512;
static constexpr int RROWS   = 8;                        // rows per block
static constexpr int VEC_PER_BLOCK = RROWS * LDIM / 4;   // 4096 float4
static constexpr long long NVEC =
    (long long)BDIM * HDIM * LDIM * LDIM / 4;            // 33,554,432
static constexpr int WIN  = LDIM + RROWS;                // 2056 window floats
static constexpr int SPAD = WIN + (WIN >> 5) + 4;        // padded smem floats

__device__ __forceinline__ int swz(int t) { return t + (t >> 5); }

__global__ __launch_bounds__(THREADS)
void urpe_mul_kernel(const float4* __restrict__ probs,
                     const float*  __restrict__ w,
                     float4*       __restrict__ out) {
    __shared__ float sg[SPAD];

    const int tid = threadIdx.x;
    // Block -> 8 consecutive rows of one (b,h) slab.
    const int rows_global = blockIdx.x * RROWS;
    const int i0 = rows_global & (LDIM - 1);
    const int h  = (rows_global >> 11) & (HDIM - 1);

    const unsigned int vbase = blockIdx.x * VEC_PER_BLOCK;

    // ---- Phase 1a: front-batch first 4 stream loads (overlap with smem fill)
    float4 v[4];
#pragma unroll
    for (int k = 0; k < 4; k++)
        v[k] = __ldcs(&probs[vbase + k * THREADS + tid]);

    // ---- Phase 1b: stage shared g-window: sg[t] = g[h, lo + t]
    // lo = L - i0 - (R-1); m ranges [lo, lo+WIN) subset of [1, 2L] (guard top).
    {
        const int lo = LDIM - i0 - (RROWS - 1);
        const float* __restrict__ whead = w + h * (2 * LDIM);
        for (int t = tid; t < WIN; t += THREADS) {
            int m = lo + t;
            if (m <= 2 * LDIM - 1) {
                int widx = (m >= LDIM) ? m : (LDIM - m);
                sg[swz(t)] = __ldg(whead + widx);
            }
        }
    }
    __syncthreads();

    // ---- Phase 2: chunk A — multiply via smem, store
#pragma unroll
    for (int k = 0; k < 4; k++) {
        int lv = k * THREADS + tid;           // 0..2047
        int r  = lv >> 9;                     // local row 0..3
        int j0 = (lv & 511) << 2;             // start column
        int t0 = j0 + (RROWS - 1) - r;        // smem window index
        v[k].x *= sg[swz(t0 + 0)];
        v[k].y *= sg[swz(t0 + 1)];
        v[k].z *= sg[swz(t0 + 2)];
        v[k].w *= sg[swz(t0 + 3)];
        __stcs(&out[vbase + lv], v[k]);
    }

    // ---- Phase 3: chunk B — front-batch loads, multiply, store
    float4 u[4];
#pragma unroll
    for (int k = 0; k < 4; k++)
        u[k] = __ldcs(&probs[vbase + (k + 4) * THREADS + tid]);

#pragma unroll
    for (int k = 0; k < 4; k++) {
        int lv = (k + 4) * THREADS + tid;     // 2048..4095
        int r  = lv >> 9;                     // local row 4..7
        int j0 = (lv & 511) << 2;
        int t0 = j0 + (RROWS - 1) - r;
        u[k].x *= sg[swz(t0 + 0)];
        u[k].y *= sg[swz(t0 + 1)];
        u[k].z *= sg[swz(t0 + 2)];
        u[k].w *= sg[swz(t0 + 3)];
        __stcs(&out[vbase + lv], u[k]);
    }
}

extern "C" void kernel_launch(void* const* d_in, const int* in_sizes, int n_in,
                              void* d_out, int out_size) {
    const float4* probs = (const float4*)d_in[0];   // attention_probs [B,H,L,L] f32
    const float*  w     = (const float*)d_in[1];    // urpe_weight_    [H,2L]   f32
    float4*       out   = (float4*)d_out;

    const int blocks = (int)(NVEC / VEC_PER_BLOCK);  // 8192, exact
    urpe_mul_kernel<<<blocks, THREADS>>>(probs, w, out);
}